// round 14
// baseline (speedup 1.0000x reference)
#include <cuda_runtime.h>
#include <math.h>

// Pines algorithm, degree N=64, B=65536 — single kernel, one wave.
// R14 = R13 (8 pts/thread = 4 f32x2 chains, 8-way column split m=8c+j,
// j-interleaved records, register double-buffer prefetch, 147x448) +
// w-rescaled recurrence (R11 algebra): w_l = w_{l-2}/n2n_l makes the b2
// coefficient exactly rho^2, so the inner step is 5 packed ops per term:
//   m1 = mul2(n1', b1); t2 = mul2(rhosq, b2); b = fma2(urho, m1, t2);
//   aC += b*c'; aS += b*s';
// The rescale weights are built IN PARALLEL per entry (iw_l = product of
// n2n down the parity chain; one fdividef per entry) — no serial walker.

#define N_DEG 64
#define CDIM  67
#define TPB   448
#define NCH   4

typedef unsigned long long u64;

static __constant__ float c_MU   = 398600441800000.0f;
static __constant__ float c_AREF = 6378136.3f;

// 281 records x 192B (record 280 = zero pad for the last prefetch).
#define NREC       281
#define MAIN_BYTES (NREC * 192)               // 53952
#define SEED_OFF   MAIN_BYTES                 // 64 x 48B
#define TAIL_OFF   (SEED_OFF + 3072)          // 24B (+pad)
#define N2N_OFF    (TAIL_OFF + 32)            // 280*8 floats raw n2n scratch
#define DIAG_OFF   (N2N_OFF + 280 * 8 * 4)    // 66 floats
#define SMEM_BYTES (DIAG_OFF + 66 * 4)

__device__ __forceinline__ int offs_c(int c) { return c * (67 - 4 * c); }

// ---------------------------------------------------------------------------
__device__ __forceinline__ u64 fma2(u64 a, u64 b, u64 c) {
    u64 d; asm("fma.rn.f32x2 %0, %1, %2, %3;" : "=l"(d) : "l"(a), "l"(b), "l"(c));
    return d;
}
__device__ __forceinline__ u64 mul2(u64 a, u64 b) {
    u64 d; asm("mul.rn.f32x2 %0, %1, %2;" : "=l"(d) : "l"(a), "l"(b));
    return d;
}
__device__ __forceinline__ u64 add2(u64 a, u64 b) {
    u64 d; asm("add.rn.f32x2 %0, %1, %2;" : "=l"(d) : "l"(a), "l"(b));
    return d;
}
__device__ __forceinline__ u64 pack2(float lo, float hi) {
    u64 d; asm("mov.b64 %0, {%1, %2};" : "=l"(d) : "f"(lo), "f"(hi));
    return d;
}
__device__ __forceinline__ void unpack2(u64 v, float& lo, float& hi) {
    asm("mov.b64 {%0, %1}, %2;" : "=f"(lo), "=f"(hi) : "l"(v));
}
__device__ __forceinline__ u64 dupf(float x) {
    unsigned int b = __float_as_uint(x);
    return ((u64)b << 32) | (u64)b;
}
__device__ __forceinline__ float lo32(u64 v) {
    return __uint_as_float((unsigned int)v);
}

// ---------------------------------------------------------------------------
__global__ void __launch_bounds__(TPB)
pines_kernel(const float4* __restrict__ inp,
             const float*  __restrict__ cBar,
             const float*  __restrict__ sBar,
             float2*       __restrict__ out, int octs)
{
    extern __shared__ char smem[];
    float* s_diag = (float*)(smem + DIAG_OFF);
    float* s_n2n  = (float*)(smem + N2N_OFF);

    int tid = threadIdx.x;

    // ---- diag cumprod (independent per l) ----
    if (tid < 66) {
        int l = tid;
        float d = 1.0f;
        for (int i = 1; i <= l; ++i) {
            float kl   = 2.0f;
            float klm1 = (i == 1) ? 1.0f : 2.0f;
            d *= sqrtf((2.0f * i + 1.0f) * kl / (2.0f * i * klm1));
        }
        s_diag[l] = d;
    }
    __syncthreads();

    // ---- seed records: (c,j) -> {dg,sd},{c0,s0},{c1,s1} (w = 1 at seeds) ----
    if (tid < 64) {
        int c = tid >> 3, j = tid & 7;
        int m = 8 * c + j;
        int l1 = m + 1;
        float kl   = 2.0f;
        float klm1 = (l1 == 1) ? 1.0f : 2.0f;
        float sub  = sqrtf(2.0f * l1 * klm1 / kl);
        float dg = s_diag[m];
        float sd = sub * s_diag[m + 1];
        float c0 = cBar[m * CDIM + m];
        float s0 = sBar[m * CDIM + m];
        if (m == 0) { c0 = 0.0f; s0 = 0.0f; }       // (0,0) term excluded
        float c1 = cBar[(m + 1) * CDIM + m];
        float s1 = sBar[(m + 1) * CDIM + m];
        ulonglong2* sp = (ulonglong2*)(smem + SEED_OFF + tid * 48);
        sp[0] = make_ulonglong2(dupf(dg), dupf(sd));
        sp[1] = make_ulonglong2(dupf(c0), dupf(s0));
        sp[2] = make_ulonglong2(dupf(c1), dupf(s1));
    }
    if (tid == TPB - 1) {   // tail record for m = 64
        u64* tp = (u64*)(smem + TAIL_OFF);
        tp[0] = dupf(cBar[64 * CDIM + 64]);
        tp[1] = dupf(sBar[64 * CDIM + 64]);
        tp[2] = dupf(s_diag[N_DEG]);
    }

    // ---- phase 1: raw tables (n1 dup + cs dup in records; n2n scratch) ----
    for (int t = tid; t < NREC * 8; t += TPB) {
        int e = t >> 3, j = t & 7;
        int c = 0;
        while (c < 7 && e >= offs_c(c + 1)) ++c;
        int k = e - offs_c(c);
        int m = 8 * c + j;
        int l = m + 2 + k;
        float n1 = 0.0f, n2n = 0.0f, cc = 0.0f, ss = 0.0f;
        if (e < 280 && l <= N_DEG) {
            float fl = (float)l, fm = (float)m;
            n1  = sqrtf((2.0f * fl + 1.0f) * (2.0f * fl - 1.0f) /
                        ((fl - fm) * (fl + fm)));
            n2n = -sqrtf((fl + fm - 1.0f) * (2.0f * fl + 1.0f) * (fl - fm - 1.0f) /
                         ((fl + fm) * (fl - fm) * (2.0f * fl - 3.0f)));
            cc = cBar[l * CDIM + m];
            ss = sBar[l * CDIM + m];
        }
        char* rec = smem + e * 192;
        *(u64*)(rec + j * 8) = dupf(n1);
        *(ulonglong2*)(rec + 64 + j * 16) = make_ulonglong2(dupf(cc), dupf(ss));
        if (e < 280) s_n2n[e * 8 + j] = n2n;
    }
    __syncthreads();

    // ---- phase 2: parallel per-entry w-rescale (no serial chain) ----
    // iw_l = prod_{l'=l, l-2, ... >= m+2} n2n_{l'}   (iw_{m}=iw_{m+1}=1)
    // n1' = n1 * iw_{l-1} / iw_l ; cs' = cs * iw_l.
    for (int t = tid; t < 280 * 8; t += TPB) {
        int e = t >> 3, j = t & 7;
        int c = 0;
        while (c < 7 && e >= offs_c(c + 1)) ++c;
        int k = e - offs_c(c);
        int m = 8 * c + j;
        int l = m + 2 + k;
        if (l > N_DEG) continue;
        int e0 = offs_c(c);
        float iwl = 1.0f, iwl1 = 1.0f;
        for (int kk = k; kk >= 0; kk -= 2)
            iwl *= s_n2n[(e0 + kk) * 8 + j];
        for (int kk = k - 1; kk >= 0; kk -= 2)
            iwl1 *= s_n2n[(e0 + kk) * 8 + j];
        char* rec = smem + e * 192;
        u64* pn1 = (u64*)(rec + j * 8);
        float n1p = lo32(*pn1) * __fdividef(iwl1, iwl);
        *pn1 = dupf(n1p);
        ulonglong2* pcs = (ulonglong2*)(rec + 64 + j * 16);
        ulonglong2 cs = *pcs;
        *pcs = make_ulonglong2(dupf(lo32(cs.x) * iwl), dupf(lo32(cs.y) * iwl));
    }
    __syncthreads();

    int g = blockIdx.x * TPB + tid;
    int j = g & 7;          // column-set id within the lane-octet
    int q = g >> 3;         // point-octet index
    bool valid = (q < octs);
    if (!valid) q = octs - 1;

    const float4* pv = inp + 8 * q;

    // ---- chain state (4 chains = 8 points) ----
    u64 urho[NCH], rhosq[NCH], rho8[NCH], rm[NCH], acc[NCH];
    u64 cre[NCH], cim[NCH], p8r[NCH], p8i[NCH];
    u64 negone = pack2(-1.0f, -1.0f);

    #pragma unroll
    for (int i = 0; i < NCH; ++i) {
        float4 v0 = pv[2 * i], v1 = pv[2 * i + 1];
        u64 rho = pack2(c_AREF / v0.x, c_AREF / v1.x);
        u64 mu  = pack2(c_MU  / v0.x, c_MU  / v1.x);
        u64 s2  = pack2(v0.y, v1.y);
        u64 t2  = pack2(v0.z, v1.z);
        u64 nt2 = mul2(t2, negone);
        u64 uu  = pack2(v0.w, v1.w);
        urho[i]  = mul2(uu, rho);
        rhosq[i] = mul2(rho, rho);
        u64 rho4 = mul2(rhosq[i], rhosq[i]);
        rho8[i]  = mul2(rho4, rho4);
        // (s+it)^8 by repeated squaring
        u64 p2r = fma2(s2, s2, mul2(nt2, t2));
        u64 st  = mul2(s2, t2);
        u64 p2i = add2(st, st);
        u64 p4r = fma2(p2r, p2r, mul2(mul2(p2i, p2i), negone));
        u64 rr  = mul2(p2r, p2i);
        u64 p4i = add2(rr, rr);
        p8r[i]  = fma2(p4r, p4r, mul2(mul2(p4i, p4i), negone));
        u64 qq  = mul2(p4r, p4i);
        p8i[i]  = add2(qq, qq);
        // start at column m = j
        u64 cr = pack2(1.0f, 1.0f), ci = 0ULL, r = mu;
        for (int it = 0; it < j; ++it) {
            u64 nr = fma2(s2, cr, mul2(nt2, ci));
            u64 ni = fma2(s2, ci, mul2(t2, cr));
            cr = nr; ci = ni;
            r = mul2(r, rho);
        }
        cre[i] = cr; cim[i] = ci; rm[i] = r;
        acc[i] = (j == 0) ? mu : 0ULL;     // MU/r leading term, once
    }

    // ---- column walk: m = 8c + j, c = 0..7 ----
    #pragma unroll 1
    for (int c = 0; c < 8; ++c) {
        const ulonglong2* sp =
            (const ulonglong2*)(smem + SEED_OFF + (c * 8 + j) * 48);
        ulonglong2 dgsd = sp[0], cs0 = sp[1], cs1 = sp[2];

        u64 b1[NCH], b2[NCH], aC[NCH], aS[NCH];
        #pragma unroll
        for (int i = 0; i < NCH; ++i) {
            b2[i] = mul2(rm[i], dgsd.x);                     // l = m   (w=1)
            b1[i] = mul2(mul2(rm[i], urho[i]), dgsd.y);      // l = m+1 (w=1)
            aC[i] = mul2(b2[i], cs0.x);
            aS[i] = mul2(b2[i], cs0.y);
            aC[i] = fma2(b1[i], cs1.x, aC[i]);
            aS[i] = fma2(b1[i], cs1.y, aS[i]);
        }

        const char* pj8  = smem + offs_c(c) * 192 + j * 8;
        const char* pj16 = smem + offs_c(c) * 192 + 64 + j * 16;
        int n = 63 - 8 * c;                                  // uniform (padded)

        // software pipeline: prefetch record k+1, compute record k
        u64        n1_c = *(const u64*)(pj8);
        ulonglong2 cs_c = *(const ulonglong2*)(pj16);
        pj8 += 192; pj16 += 192;

        #pragma unroll 2
        for (int k = 0; k < n - 1; ++k) {
            u64        n1_x = *(const u64*)(pj8);
            ulonglong2 cs_x = *(const ulonglong2*)(pj16);
            pj8 += 192; pj16 += 192;
            #pragma unroll
            for (int i = 0; i < NCH; ++i) {
                u64 t2 = mul2(rhosq[i], b2[i]);      // off critical path
                u64 m1 = mul2(n1_c, b1[i]);          // critical
                u64 b  = fma2(urho[i], m1, t2);
                aC[i] = fma2(b, cs_c.x, aC[i]);
                aS[i] = fma2(b, cs_c.y, aS[i]);
                b2[i] = b1[i];
                b1[i] = b;
            }
            n1_c = n1_x;
            cs_c = cs_x;
        }
        // last record of this column block
        #pragma unroll
        for (int i = 0; i < NCH; ++i) {
            u64 t2 = mul2(rhosq[i], b2[i]);
            u64 m1 = mul2(n1_c, b1[i]);
            u64 b  = fma2(urho[i], m1, t2);
            aC[i] = fma2(b, cs_c.x, aC[i]);
            aS[i] = fma2(b, cs_c.y, aS[i]);
            b2[i] = b1[i];
            b1[i] = b;
        }

        #pragma unroll
        for (int i = 0; i < NCH; ++i) {
            acc[i] = fma2(cre[i], aC[i], acc[i]);
            acc[i] = fma2(cim[i], aS[i], acc[i]);
            // jump 8 columns: phasor *= (s+it)^8, rm *= rho^8
            u64 nr = fma2(mul2(cim[i], p8i[i]), negone, mul2(cre[i], p8r[i]));
            u64 ni = fma2(cim[i], p8r[i], mul2(cre[i], p8i[i]));
            cre[i] = nr; cim[i] = ni;
            rm[i] = mul2(rm[i], rho8[i]);
        }
    }

    // tail column m = 64 (j==0 lanes are exactly at m=64 now)
    if (j == 0) {
        const u64* tp = (const u64*)(smem + TAIL_OFF);
        u64 c64 = tp[0], s64 = tp[1], dg64 = tp[2];
        #pragma unroll
        for (int i = 0; i < NCH; ++i) {
            u64 b = mul2(rm[i], dg64);
            acc[i] = fma2(cre[i], mul2(b, c64), acc[i]);
            acc[i] = fma2(cim[i], mul2(b, s64), acc[i]);
        }
    }

    // combine 8 column-set partials within each lane-octet
    #pragma unroll
    for (int i = 0; i < NCH; ++i) {
        u64 a = acc[i];
        a = add2(a, __shfl_xor_sync(0xffffffffu, a, 1));
        a = add2(a, __shfl_xor_sync(0xffffffffu, a, 2));
        a = add2(a, __shfl_xor_sync(0xffffffffu, a, 4));
        acc[i] = a;
    }

    if (valid && j == 0) {
        #pragma unroll
        for (int i = 0; i < NCH; ++i) {
            float lo, hi;
            unpack2(acc[i], lo, hi);
            out[4 * q + i] = make_float2(-lo, -hi);
        }
    }
}

// ---------------------------------------------------------------------------
extern "C" void kernel_launch(void* const* d_in, const int* in_sizes, int n_in,
                              void* d_out, int out_size)
{
    const float* inputs = (const float*)d_in[0];  // [B,4] : r,s,t,u
    const float* cBar   = (const float*)d_in[1];  // [67,67]
    const float* sBar   = (const float*)d_in[2];  // [67,67]
    float*       out    = (float*)d_out;          // [B]

    int B    = in_sizes[0] / 4;
    int octs = B / 8;                             // 8192 point-octets

    cudaFuncSetAttribute(pines_kernel,
                         cudaFuncAttributeMaxDynamicSharedMemorySize,
                         SMEM_BYTES);

    int threads_total = octs * 8;                 // 65536
    int blocks = (threads_total + TPB - 1) / TPB; // 147
    pines_kernel<<<blocks, TPB, SMEM_BYTES>>>(
        (const float4*)inputs, cBar, sBar, (float2*)out, octs);
}

// round 15
// speedup vs baseline: 1.4085x; 1.4085x over previous
#include <cuda_runtime.h>
#include <math.h>

// Pines algorithm, degree N=64, B=65536 — prep kernel + main kernel.
// R15 = R13 structure (8 pts/thread = 4 f32x2 chains, 8-way column split
// m = 8c+j, j-interleaved records, register double-buffer prefetch,
// 147x448 one wave) with the R14 w-rescaled 5-op inner step:
//   m1 = mul2(n1', b1); t2 = mul2(rhosq, b2); b = fma2(urho, m1, t2);
//   aC += b*c'; aS += b*s';
// The rescaled table is built ONCE by a 1-block prep kernel (serial 63-step
// walker per column, 64 walkers in parallel, all in ITS smem) and written to
// a __device__ global; the main kernel bulk-copies it to smem (L2-resident).

#define N_DEG 64
#define CDIM  67
#define TPB   448
#define NCH   4

typedef unsigned long long u64;

static __constant__ float c_MU   = 398600441800000.0f;
static __constant__ float c_AREF = 6378136.3f;

// 281 records x 192B (record 280 = zero pad for the last prefetch).
#define NREC       281
#define MAIN_BYTES (NREC * 192)                  // 53952
#define SEED_OFF   MAIN_BYTES                    // 64 x 48B
#define TAIL_OFF   (SEED_OFF + 3072)             // 24B (+pad to 32)
#define TABLE_BYTES (TAIL_OFF + 32)              // 57056
#define TABLE_U64   (TABLE_BYTES / 8)            // 7132

// prep-kernel extra scratch beyond the table image
#define N2N_OFF    TABLE_BYTES                   // 280*8 floats
#define DIAG_OFF   (N2N_OFF + 280 * 8 * 4)       // 66 floats
#define PREP_SMEM  (DIAG_OFF + 66 * 4)

__device__ u64 g_table[TABLE_U64];

__device__ __forceinline__ int offs_c(int c) { return c * (67 - 4 * c); }

// ---------------------------------------------------------------------------
__device__ __forceinline__ u64 fma2(u64 a, u64 b, u64 c) {
    u64 d; asm("fma.rn.f32x2 %0, %1, %2, %3;" : "=l"(d) : "l"(a), "l"(b), "l"(c));
    return d;
}
__device__ __forceinline__ u64 mul2(u64 a, u64 b) {
    u64 d; asm("mul.rn.f32x2 %0, %1, %2;" : "=l"(d) : "l"(a), "l"(b));
    return d;
}
__device__ __forceinline__ u64 add2(u64 a, u64 b) {
    u64 d; asm("add.rn.f32x2 %0, %1, %2;" : "=l"(d) : "l"(a), "l"(b));
    return d;
}
__device__ __forceinline__ u64 pack2(float lo, float hi) {
    u64 d; asm("mov.b64 %0, {%1, %2};" : "=l"(d) : "f"(lo), "f"(hi));
    return d;
}
__device__ __forceinline__ void unpack2(u64 v, float& lo, float& hi) {
    asm("mov.b64 {%0, %1}, %2;" : "=f"(lo), "=f"(hi) : "l"(v));
}
__device__ __forceinline__ u64 dupf(float x) {
    unsigned int b = __float_as_uint(x);
    return ((u64)b << 32) | (u64)b;
}
__device__ __forceinline__ float lo32(u64 v) {
    return __uint_as_float((unsigned int)v);
}

// ---------------------------------------------------------------------------
// Prep kernel — ONE block. Builds the finished (w-rescaled) table in its own
// shared memory, then copies it to g_table.
// ---------------------------------------------------------------------------
__global__ void __launch_bounds__(512)
pines_prep(const float* __restrict__ cBar, const float* __restrict__ sBar)
{
    extern __shared__ char smem[];
    float* s_diag = (float*)(smem + DIAG_OFF);
    float* s_n2n  = (float*)(smem + N2N_OFF);

    int tid = threadIdx.x;

    // diag cumprod (independent per l)
    if (tid < 66) {
        int l = tid;
        float d = 1.0f;
        for (int i = 1; i <= l; ++i) {
            float kl   = 2.0f;
            float klm1 = (i == 1) ? 1.0f : 2.0f;
            d *= sqrtf((2.0f * i + 1.0f) * kl / (2.0f * i * klm1));
        }
        s_diag[l] = d;
    }
    __syncthreads();

    // seed records: (c,j) -> {dg,sd},{c0,s0},{c1,s1}  (w = 1 at seeds)
    if (tid < 64) {
        int c = tid >> 3, j = tid & 7;
        int m = 8 * c + j;
        int l1 = m + 1;
        float kl   = 2.0f;
        float klm1 = (l1 == 1) ? 1.0f : 2.0f;
        float sub  = sqrtf(2.0f * l1 * klm1 / kl);
        float dg = s_diag[m];
        float sd = sub * s_diag[m + 1];
        float c0 = cBar[m * CDIM + m];
        float s0 = sBar[m * CDIM + m];
        if (m == 0) { c0 = 0.0f; s0 = 0.0f; }       // (0,0) term excluded
        float c1 = cBar[(m + 1) * CDIM + m];
        float s1 = sBar[(m + 1) * CDIM + m];
        ulonglong2* sp = (ulonglong2*)(smem + SEED_OFF + tid * 48);
        sp[0] = make_ulonglong2(dupf(dg), dupf(sd));
        sp[1] = make_ulonglong2(dupf(c0), dupf(s0));
        sp[2] = make_ulonglong2(dupf(c1), dupf(s1));
    }
    if (tid == 511) {   // tail record for m = 64
        u64* tp = (u64*)(smem + TAIL_OFF);
        tp[0] = dupf(cBar[64 * CDIM + 64]);
        tp[1] = dupf(sBar[64 * CDIM + 64]);
        tp[2] = dupf(s_diag[N_DEG]);
        tp[3] = 0ULL;
    }

    // raw table: n1 dup + cs dup in records; n2n in scratch
    for (int t = tid; t < NREC * 8; t += 512) {
        int e = t >> 3, j = t & 7;
        int c = 0;
        while (c < 7 && e >= offs_c(c + 1)) ++c;
        int k = e - offs_c(c);
        int m = 8 * c + j;
        int l = m + 2 + k;
        float n1 = 0.0f, n2n = 0.0f, cc = 0.0f, ss = 0.0f;
        if (e < 280 && l <= N_DEG) {
            float fl = (float)l, fm = (float)m;
            n1  = sqrtf((2.0f * fl + 1.0f) * (2.0f * fl - 1.0f) /
                        ((fl - fm) * (fl + fm)));
            n2n = -sqrtf((fl + fm - 1.0f) * (2.0f * fl + 1.0f) * (fl - fm - 1.0f) /
                         ((fl + fm) * (fl - fm) * (2.0f * fl - 3.0f)));
            cc = cBar[l * CDIM + m];
            ss = sBar[l * CDIM + m];
        }
        char* rec = smem + e * 192;
        *(u64*)(rec + j * 8) = dupf(n1);
        *(ulonglong2*)(rec + 64 + j * 16) = make_ulonglong2(dupf(cc), dupf(ss));
        if (e < 280) s_n2n[e * 8 + j] = n2n;
    }
    __syncthreads();

    // w-rescale: one serial walker per column m (64 walkers in parallel).
    // iw_l = iw_{l-2} * n2n_l  (iw_m = iw_{m+1} = 1)
    // n1'_l = n1_l * iw_{l-1}/iw_l ;  cs'_l = cs_l * iw_l.
    if (tid < 64) {
        int m = tid;
        int c = m >> 3, j = m & 7;
        int e0 = offs_c(c);
        float iw2 = 1.0f, iw1 = 1.0f;
        int nreal = 63 - m;
        for (int k = 0; k < nreal; ++k) {
            int e = e0 + k;
            float n2n = s_n2n[e * 8 + j];
            float iwl = iw2 * n2n;
            char* rec = smem + e * 192;
            u64* pn1 = (u64*)(rec + j * 8);
            float n1p = lo32(*pn1) * __fdividef(iw1, iwl);
            *pn1 = dupf(n1p);
            ulonglong2* pcs = (ulonglong2*)(rec + 64 + j * 16);
            ulonglong2 cs = *pcs;
            *pcs = make_ulonglong2(dupf(lo32(cs.x) * iwl), dupf(lo32(cs.y) * iwl));
            iw2 = iw1; iw1 = iwl;
        }
    }
    __syncthreads();

    // publish the finished table
    const u64* src = (const u64*)smem;
    for (int i = tid; i < TABLE_U64; i += 512)
        g_table[i] = src[i];
}

// ---------------------------------------------------------------------------
// Main kernel
// ---------------------------------------------------------------------------
__global__ void __launch_bounds__(TPB)
pines_kernel(const float4* __restrict__ inp,
             float2* __restrict__ out, int octs)
{
    extern __shared__ char smem[];

    int tid = threadIdx.x;

    // copy finished table from global (L2-resident after block 0's miss)
    {
        u64* dst = (u64*)smem;
        #pragma unroll 4
        for (int i = tid; i < TABLE_U64; i += TPB)
            dst[i] = g_table[i];
    }
    __syncthreads();

    int g = blockIdx.x * TPB + tid;
    int j = g & 7;          // column-set id within the lane-octet
    int q = g >> 3;         // point-octet index
    bool valid = (q < octs);
    if (!valid) q = octs - 1;

    const float4* pv = inp + 8 * q;

    // ---- chain state (4 chains = 8 points) ----
    u64 urho[NCH], rhosq[NCH], rho8[NCH], rm[NCH], acc[NCH];
    u64 cre[NCH], cim[NCH], p8r[NCH], p8i[NCH];
    u64 negone = pack2(-1.0f, -1.0f);

    #pragma unroll
    for (int i = 0; i < NCH; ++i) {
        float4 v0 = pv[2 * i], v1 = pv[2 * i + 1];
        u64 rho = pack2(c_AREF / v0.x, c_AREF / v1.x);
        u64 mu  = pack2(c_MU  / v0.x, c_MU  / v1.x);
        u64 s2  = pack2(v0.y, v1.y);
        u64 t2  = pack2(v0.z, v1.z);
        u64 nt2 = mul2(t2, negone);
        u64 uu  = pack2(v0.w, v1.w);
        urho[i]  = mul2(uu, rho);
        rhosq[i] = mul2(rho, rho);
        u64 rho4 = mul2(rhosq[i], rhosq[i]);
        rho8[i]  = mul2(rho4, rho4);
        // (s+it)^8 by repeated squaring
        u64 p2r = fma2(s2, s2, mul2(nt2, t2));
        u64 st  = mul2(s2, t2);
        u64 p2i = add2(st, st);
        u64 p4r = fma2(p2r, p2r, mul2(mul2(p2i, p2i), negone));
        u64 rr  = mul2(p2r, p2i);
        u64 p4i = add2(rr, rr);
        p8r[i]  = fma2(p4r, p4r, mul2(mul2(p4i, p4i), negone));
        u64 qq  = mul2(p4r, p4i);
        p8i[i]  = add2(qq, qq);
        // start at column m = j
        u64 cr = pack2(1.0f, 1.0f), ci = 0ULL, r = mu;
        for (int it = 0; it < j; ++it) {
            u64 nr = fma2(s2, cr, mul2(nt2, ci));
            u64 ni = fma2(s2, ci, mul2(t2, cr));
            cr = nr; ci = ni;
            r = mul2(r, rho);
        }
        cre[i] = cr; cim[i] = ci; rm[i] = r;
        acc[i] = (j == 0) ? mu : 0ULL;     // MU/r leading term, once
    }

    // ---- column walk: m = 8c + j, c = 0..7 ----
    #pragma unroll 1
    for (int c = 0; c < 8; ++c) {
        const ulonglong2* sp =
            (const ulonglong2*)(smem + SEED_OFF + (c * 8 + j) * 48);
        ulonglong2 dgsd = sp[0], cs0 = sp[1], cs1 = sp[2];

        u64 b1[NCH], b2[NCH], aC[NCH], aS[NCH];
        #pragma unroll
        for (int i = 0; i < NCH; ++i) {
            b2[i] = mul2(rm[i], dgsd.x);                     // l = m   (w=1)
            b1[i] = mul2(mul2(rm[i], urho[i]), dgsd.y);      // l = m+1 (w=1)
            aC[i] = mul2(b2[i], cs0.x);
            aS[i] = mul2(b2[i], cs0.y);
            aC[i] = fma2(b1[i], cs1.x, aC[i]);
            aS[i] = fma2(b1[i], cs1.y, aS[i]);
        }

        const char* pj8  = smem + offs_c(c) * 192 + j * 8;
        const char* pj16 = smem + offs_c(c) * 192 + 64 + j * 16;
        int n = 63 - 8 * c;                                  // uniform (padded)

        // software pipeline: prefetch record k+1, compute record k
        u64        n1_c = *(const u64*)(pj8);
        ulonglong2 cs_c = *(const ulonglong2*)(pj16);
        pj8 += 192; pj16 += 192;

        #pragma unroll 2
        for (int k = 0; k < n - 1; ++k) {
            u64        n1_x = *(const u64*)(pj8);
            ulonglong2 cs_x = *(const ulonglong2*)(pj16);
            pj8 += 192; pj16 += 192;
            #pragma unroll
            for (int i = 0; i < NCH; ++i) {
                u64 t2 = mul2(rhosq[i], b2[i]);      // off critical path
                u64 m1 = mul2(n1_c, b1[i]);          // critical
                u64 b  = fma2(urho[i], m1, t2);
                aC[i] = fma2(b, cs_c.x, aC[i]);
                aS[i] = fma2(b, cs_c.y, aS[i]);
                b2[i] = b1[i];
                b1[i] = b;
            }
            n1_c = n1_x;
            cs_c = cs_x;
        }
        // last record of this column block
        #pragma unroll
        for (int i = 0; i < NCH; ++i) {
            u64 t2 = mul2(rhosq[i], b2[i]);
            u64 m1 = mul2(n1_c, b1[i]);
            u64 b  = fma2(urho[i], m1, t2);
            aC[i] = fma2(b, cs_c.x, aC[i]);
            aS[i] = fma2(b, cs_c.y, aS[i]);
            b2[i] = b1[i];
            b1[i] = b;
        }

        #pragma unroll
        for (int i = 0; i < NCH; ++i) {
            acc[i] = fma2(cre[i], aC[i], acc[i]);
            acc[i] = fma2(cim[i], aS[i], acc[i]);
            // jump 8 columns: phasor *= (s+it)^8, rm *= rho^8
            u64 nr = fma2(mul2(cim[i], p8i[i]), negone, mul2(cre[i], p8r[i]));
            u64 ni = fma2(cim[i], p8r[i], mul2(cre[i], p8i[i]));
            cre[i] = nr; cim[i] = ni;
            rm[i] = mul2(rm[i], rho8[i]);
        }
    }

    // tail column m = 64 (j==0 lanes are exactly at m=64 now)
    if (j == 0) {
        const u64* tp = (const u64*)(smem + TAIL_OFF);
        u64 c64 = tp[0], s64 = tp[1], dg64 = tp[2];
        #pragma unroll
        for (int i = 0; i < NCH; ++i) {
            u64 b = mul2(rm[i], dg64);
            acc[i] = fma2(cre[i], mul2(b, c64), acc[i]);
            acc[i] = fma2(cim[i], mul2(b, s64), acc[i]);
        }
    }

    // combine 8 column-set partials within each lane-octet
    #pragma unroll
    for (int i = 0; i < NCH; ++i) {
        u64 a = acc[i];
        a = add2(a, __shfl_xor_sync(0xffffffffu, a, 1));
        a = add2(a, __shfl_xor_sync(0xffffffffu, a, 2));
        a = add2(a, __shfl_xor_sync(0xffffffffu, a, 4));
        acc[i] = a;
    }

    if (valid && j == 0) {
        #pragma unroll
        for (int i = 0; i < NCH; ++i) {
            float lo, hi;
            unpack2(acc[i], lo, hi);
            out[4 * q + i] = make_float2(-lo, -hi);
        }
    }
}

// ---------------------------------------------------------------------------
extern "C" void kernel_launch(void* const* d_in, const int* in_sizes, int n_in,
                              void* d_out, int out_size)
{
    const float* inputs = (const float*)d_in[0];  // [B,4] : r,s,t,u
    const float* cBar   = (const float*)d_in[1];  // [67,67]
    const float* sBar   = (const float*)d_in[2];  // [67,67]
    float*       out    = (float*)d_out;          // [B]

    int B    = in_sizes[0] / 4;
    int octs = B / 8;                             // 8192 point-octets

    cudaFuncSetAttribute(pines_prep,
                         cudaFuncAttributeMaxDynamicSharedMemorySize,
                         PREP_SMEM);
    cudaFuncSetAttribute(pines_kernel,
                         cudaFuncAttributeMaxDynamicSharedMemorySize,
                         TABLE_BYTES);

    pines_prep<<<1, 512, PREP_SMEM>>>(cBar, sBar);

    int threads_total = octs * 8;                 // 65536
    int blocks = (threads_total + TPB - 1) / TPB; // 147
    pines_kernel<<<blocks, TPB, TABLE_BYTES>>>(
        (const float4*)inputs, (float2*)out, octs);
}

// round 16
// speedup vs baseline: 1.6510x; 1.1722x over previous
#include <cuda_runtime.h>
#include <math.h>

// Pines algorithm, degree N=64, B=65536 — single kernel, one wave.
// R16 = R15 main loop (8 pts/thread = 4 f32x2 chains, 8-way column split
// m = 8c+j, j-interleaved 192B records, register double-buffer prefetch,
// w-rescaled 5-op inner step) with the rescaled table built PER BLOCK using
// parallel log-scans (Hillis-Steele product scans in smem ping-pong buffers)
// instead of R15's one-block serial-walker prep kernel (-14us of prep+gap):
//   diag  = cumprod(f_l)             : 7 scan steps
//   P[k]  = prod n2n down parity chain: 6 scan steps (P[k] *= P[k-2s])
//   n1'_l = n1 * P[k-1]/P[k] ; cs'_l = cs * P[k]   (one fdividef per entry)

#define N_DEG 64
#define CDIM  67
#define TPB   448
#define NCH   4

typedef unsigned long long u64;

static __constant__ float c_MU   = 398600441800000.0f;
static __constant__ float c_AREF = 6378136.3f;

// 281 records x 192B (record 280 = zero pad for the last prefetch).
#define NREC       281
#define MAIN_BYTES (NREC * 192)                  // 53952
#define SEED_OFF   MAIN_BYTES                    // 64 x 48B
#define TAIL_OFF   (SEED_OFF + 3072)             // 32B
#define TABLE_BYTES (TAIL_OFF + 32)              // 57056
// scan scratch (ping-pong)
#define PA_OFF     TABLE_BYTES                   // 280*8 floats
#define PB_OFF     (PA_OFF + 280 * 8 * 4)        // 280*8 floats
#define DA_OFF     (PB_OFF + 280 * 8 * 4)        // 66 floats
#define DB_OFF     (DA_OFF + 66 * 4)             // 66 floats
#define SMEM_BYTES (DB_OFF + 66 * 4)

__device__ __forceinline__ int offs_c(int c) { return c * (67 - 4 * c); }

// ---------------------------------------------------------------------------
__device__ __forceinline__ u64 fma2(u64 a, u64 b, u64 c) {
    u64 d; asm("fma.rn.f32x2 %0, %1, %2, %3;" : "=l"(d) : "l"(a), "l"(b), "l"(c));
    return d;
}
__device__ __forceinline__ u64 mul2(u64 a, u64 b) {
    u64 d; asm("mul.rn.f32x2 %0, %1, %2;" : "=l"(d) : "l"(a), "l"(b));
    return d;
}
__device__ __forceinline__ u64 add2(u64 a, u64 b) {
    u64 d; asm("add.rn.f32x2 %0, %1, %2;" : "=l"(d) : "l"(a), "l"(b));
    return d;
}
__device__ __forceinline__ u64 pack2(float lo, float hi) {
    u64 d; asm("mov.b64 %0, {%1, %2};" : "=l"(d) : "f"(lo), "f"(hi));
    return d;
}
__device__ __forceinline__ void unpack2(u64 v, float& lo, float& hi) {
    asm("mov.b64 {%0, %1}, %2;" : "=f"(lo), "=f"(hi) : "l"(v));
}
__device__ __forceinline__ u64 dupf(float x) {
    unsigned int b = __float_as_uint(x);
    return ((u64)b << 32) | (u64)b;
}
__device__ __forceinline__ float lo32(u64 v) {
    return __uint_as_float((unsigned int)v);
}

// ---------------------------------------------------------------------------
__global__ void __launch_bounds__(TPB)
pines_kernel(const float4* __restrict__ inp,
             const float*  __restrict__ cBar,
             const float*  __restrict__ sBar,
             float2*       __restrict__ out, int octs)
{
    extern __shared__ char smem[];
    int tid = threadIdx.x;

    // ======================= per-block table build =======================
    {
        float* dA = (float*)(smem + DA_OFF);
        float* dB = (float*)(smem + DB_OFF);
        float* PA = (float*)(smem + PA_OFF);
        float* PB = (float*)(smem + PB_OFF);

        // f_l factors (independent)
        if (tid < 66) {
            float f;
            if (tid == 0)      f = 1.0f;
            else if (tid == 1) f = sqrtf(3.0f);
            else               f = sqrtf((2.0f * tid + 1.0f) / (2.0f * tid));
            dA[tid] = f;
        }

        // raw table: n1 dup + cs dup into records; n2n into PA (pads = 1.0)
        for (int t = tid; t < NREC * 8; t += TPB) {
            int e = t >> 3, j = t & 7;
            int c = 0;
            while (c < 7 && e >= offs_c(c + 1)) ++c;
            int k = e - offs_c(c);
            int m = 8 * c + j;
            int l = m + 2 + k;
            float n1 = 0.0f, n2n = 1.0f, cc = 0.0f, ss = 0.0f;
            if (e < 280 && l <= N_DEG) {
                float fl = (float)l, fm = (float)m;
                n1  = sqrtf((2.0f * fl + 1.0f) * (2.0f * fl - 1.0f) /
                            ((fl - fm) * (fl + fm)));
                n2n = -sqrtf((fl + fm - 1.0f) * (2.0f * fl + 1.0f) * (fl - fm - 1.0f) /
                             ((fl + fm) * (fl - fm) * (2.0f * fl - 3.0f)));
                cc = cBar[l * CDIM + m];
                ss = sBar[l * CDIM + m];
            }
            char* rec = smem + e * 192;
            *(u64*)(rec + j * 8) = dupf(n1);
            *(ulonglong2*)(rec + 64 + j * 16) = make_ulonglong2(dupf(cc), dupf(ss));
            if (e < 280) PA[e * 8 + j] = n2n;
        }
        __syncthreads();

        // diag = inclusive cumprod of f (7 ping-pong scan steps)
        float* ds = dA; float* dd = dB;
        for (int s = 1; s < 66; s <<= 1) {
            if (tid < 66) {
                float v = ds[tid];
                if (tid >= s) v *= ds[tid - s];
                dd[tid] = v;
            }
            __syncthreads();
            float* tmp = ds; ds = dd; dd = tmp;
        }
        // diag now in ds[]

        // P[k] = product of n2n down the stride-2 parity chain (6 steps)
        float* Ps = PA; float* Pd = PB;
        for (int s = 1; s <= 32; s <<= 1) {
            for (int t = tid; t < 280 * 8; t += TPB) {
                int e = t >> 3, j = t & 7;
                int c = 0;
                while (c < 7 && e >= offs_c(c + 1)) ++c;
                int k = e - offs_c(c);
                float v = Ps[e * 8 + j];
                if (k >= 2 * s) v *= Ps[(e - 2 * s) * 8 + j];
                Pd[e * 8 + j] = v;
            }
            __syncthreads();
            float* tmp = Ps; Ps = Pd; Pd = tmp;
        }
        // P now in Ps[]

        // seeds: (c,j) -> {dg,sd},{c0,s0},{c1,s1}  (w = 1 at seeds)
        if (tid < 64) {
            int c = tid >> 3, j = tid & 7;
            int m = 8 * c + j;
            int l1 = m + 1;
            float sub = (l1 == 1) ? 1.0f : sqrtf(2.0f * l1);
            float dg = ds[m];
            float sd = sub * ds[m + 1];
            float c0 = cBar[m * CDIM + m];
            float s0 = sBar[m * CDIM + m];
            if (m == 0) { c0 = 0.0f; s0 = 0.0f; }   // (0,0) term excluded
            float c1 = cBar[(m + 1) * CDIM + m];
            float s1 = sBar[(m + 1) * CDIM + m];
            ulonglong2* sp = (ulonglong2*)(smem + SEED_OFF + tid * 48);
            sp[0] = make_ulonglong2(dupf(dg), dupf(sd));
            sp[1] = make_ulonglong2(dupf(c0), dupf(s0));
            sp[2] = make_ulonglong2(dupf(c1), dupf(s1));
        }
        if (tid == TPB - 1) {   // tail record for m = 64
            u64* tp = (u64*)(smem + TAIL_OFF);
            tp[0] = dupf(cBar[64 * CDIM + 64]);
            tp[1] = dupf(sBar[64 * CDIM + 64]);
            tp[2] = dupf(ds[N_DEG]);
            tp[3] = 0ULL;
        }

        // apply rescale to real entries: n1' = n1*P[k-1]/P[k]; cs' = cs*P[k]
        for (int t = tid; t < 280 * 8; t += TPB) {
            int e = t >> 3, j = t & 7;
            int c = 0;
            while (c < 7 && e >= offs_c(c + 1)) ++c;
            int k = e - offs_c(c);
            int m = 8 * c + j;
            int l = m + 2 + k;
            if (l > N_DEG) continue;
            float Pk  = Ps[e * 8 + j];
            float Pk1 = (k >= 1) ? Ps[(e - 1) * 8 + j] : 1.0f;
            char* rec = smem + e * 192;
            u64* pn1 = (u64*)(rec + j * 8);
            *pn1 = dupf(lo32(*pn1) * __fdividef(Pk1, Pk));
            ulonglong2* pcs = (ulonglong2*)(rec + 64 + j * 16);
            ulonglong2 cs = *pcs;
            *pcs = make_ulonglong2(dupf(lo32(cs.x) * Pk), dupf(lo32(cs.y) * Pk));
        }
        __syncthreads();
    }
    // ========================== main compute =============================

    int g = blockIdx.x * TPB + tid;
    int j = g & 7;          // column-set id within the lane-octet
    int q = g >> 3;         // point-octet index
    bool valid = (q < octs);
    if (!valid) q = octs - 1;

    const float4* pv = inp + 8 * q;

    u64 urho[NCH], rhosq[NCH], rho8[NCH], rm[NCH], acc[NCH];
    u64 cre[NCH], cim[NCH], p8r[NCH], p8i[NCH];
    u64 negone = pack2(-1.0f, -1.0f);

    #pragma unroll
    for (int i = 0; i < NCH; ++i) {
        float4 v0 = pv[2 * i], v1 = pv[2 * i + 1];
        u64 rho = pack2(c_AREF / v0.x, c_AREF / v1.x);
        u64 mu  = pack2(c_MU  / v0.x, c_MU  / v1.x);
        u64 s2  = pack2(v0.y, v1.y);
        u64 t2  = pack2(v0.z, v1.z);
        u64 nt2 = mul2(t2, negone);
        u64 uu  = pack2(v0.w, v1.w);
        urho[i]  = mul2(uu, rho);
        rhosq[i] = mul2(rho, rho);
        u64 rho4 = mul2(rhosq[i], rhosq[i]);
        rho8[i]  = mul2(rho4, rho4);
        // (s+it)^8 by repeated squaring
        u64 p2r = fma2(s2, s2, mul2(nt2, t2));
        u64 st  = mul2(s2, t2);
        u64 p2i = add2(st, st);
        u64 p4r = fma2(p2r, p2r, mul2(mul2(p2i, p2i), negone));
        u64 rr  = mul2(p2r, p2i);
        u64 p4i = add2(rr, rr);
        p8r[i]  = fma2(p4r, p4r, mul2(mul2(p4i, p4i), negone));
        u64 qq  = mul2(p4r, p4i);
        p8i[i]  = add2(qq, qq);
        // start at column m = j
        u64 cr = pack2(1.0f, 1.0f), ci = 0ULL, r = mu;
        for (int it = 0; it < j; ++it) {
            u64 nr = fma2(s2, cr, mul2(nt2, ci));
            u64 ni = fma2(s2, ci, mul2(t2, cr));
            cr = nr; ci = ni;
            r = mul2(r, rho);
        }
        cre[i] = cr; cim[i] = ci; rm[i] = r;
        acc[i] = (j == 0) ? mu : 0ULL;     // MU/r leading term, once
    }

    // ---- column walk: m = 8c + j, c = 0..7 ----
    #pragma unroll 1
    for (int c = 0; c < 8; ++c) {
        const ulonglong2* sp =
            (const ulonglong2*)(smem + SEED_OFF + (c * 8 + j) * 48);
        ulonglong2 dgsd = sp[0], cs0 = sp[1], cs1 = sp[2];

        u64 b1[NCH], b2[NCH], aC[NCH], aS[NCH];
        #pragma unroll
        for (int i = 0; i < NCH; ++i) {
            b2[i] = mul2(rm[i], dgsd.x);                     // l = m   (w=1)
            b1[i] = mul2(mul2(rm[i], urho[i]), dgsd.y);      // l = m+1 (w=1)
            aC[i] = mul2(b2[i], cs0.x);
            aS[i] = mul2(b2[i], cs0.y);
            aC[i] = fma2(b1[i], cs1.x, aC[i]);
            aS[i] = fma2(b1[i], cs1.y, aS[i]);
        }

        const char* pj8  = smem + offs_c(c) * 192 + j * 8;
        const char* pj16 = smem + offs_c(c) * 192 + 64 + j * 16;
        int n = 63 - 8 * c;                                  // uniform (padded)

        // software pipeline: prefetch record k+1, compute record k
        u64        n1_c = *(const u64*)(pj8);
        ulonglong2 cs_c = *(const ulonglong2*)(pj16);
        pj8 += 192; pj16 += 192;

        #pragma unroll 2
        for (int k = 0; k < n - 1; ++k) {
            u64        n1_x = *(const u64*)(pj8);
            ulonglong2 cs_x = *(const ulonglong2*)(pj16);
            pj8 += 192; pj16 += 192;
            #pragma unroll
            for (int i = 0; i < NCH; ++i) {
                u64 t2 = mul2(rhosq[i], b2[i]);      // off critical path
                u64 m1 = mul2(n1_c, b1[i]);          // critical
                u64 b  = fma2(urho[i], m1, t2);
                aC[i] = fma2(b, cs_c.x, aC[i]);
                aS[i] = fma2(b, cs_c.y, aS[i]);
                b2[i] = b1[i];
                b1[i] = b;
            }
            n1_c = n1_x;
            cs_c = cs_x;
        }
        // last record of this column block
        #pragma unroll
        for (int i = 0; i < NCH; ++i) {
            u64 t2 = mul2(rhosq[i], b2[i]);
            u64 m1 = mul2(n1_c, b1[i]);
            u64 b  = fma2(urho[i], m1, t2);
            aC[i] = fma2(b, cs_c.x, aC[i]);
            aS[i] = fma2(b, cs_c.y, aS[i]);
            b2[i] = b1[i];
            b1[i] = b;
        }

        #pragma unroll
        for (int i = 0; i < NCH; ++i) {
            acc[i] = fma2(cre[i], aC[i], acc[i]);
            acc[i] = fma2(cim[i], aS[i], acc[i]);
            // jump 8 columns: phasor *= (s+it)^8, rm *= rho^8
            u64 nr = fma2(mul2(cim[i], p8i[i]), negone, mul2(cre[i], p8r[i]));
            u64 ni = fma2(cim[i], p8r[i], mul2(cre[i], p8i[i]));
            cre[i] = nr; cim[i] = ni;
            rm[i] = mul2(rm[i], rho8[i]);
        }
    }

    // tail column m = 64 (j==0 lanes are exactly at m=64 now)
    if (j == 0) {
        const u64* tp = (const u64*)(smem + TAIL_OFF);
        u64 c64 = tp[0], s64 = tp[1], dg64 = tp[2];
        #pragma unroll
        for (int i = 0; i < NCH; ++i) {
            u64 b = mul2(rm[i], dg64);
            acc[i] = fma2(cre[i], mul2(b, c64), acc[i]);
            acc[i] = fma2(cim[i], mul2(b, s64), acc[i]);
        }
    }

    // combine 8 column-set partials within each lane-octet
    #pragma unroll
    for (int i = 0; i < NCH; ++i) {
        u64 a = acc[i];
        a = add2(a, __shfl_xor_sync(0xffffffffu, a, 1));
        a = add2(a, __shfl_xor_sync(0xffffffffu, a, 2));
        a = add2(a, __shfl_xor_sync(0xffffffffu, a, 4));
        acc[i] = a;
    }

    if (valid && j == 0) {
        #pragma unroll
        for (int i = 0; i < NCH; ++i) {
            float lo, hi;
            unpack2(acc[i], lo, hi);
            out[4 * q + i] = make_float2(-lo, -hi);
        }
    }
}

// ---------------------------------------------------------------------------
extern "C" void kernel_launch(void* const* d_in, const int* in_sizes, int n_in,
                              void* d_out, int out_size)
{
    const float* inputs = (const float*)d_in[0];  // [B,4] : r,s,t,u
    const float* cBar   = (const float*)d_in[1];  // [67,67]
    const float* sBar   = (const float*)d_in[2];  // [67,67]
    float*       out    = (float*)d_out;          // [B]

    int B    = in_sizes[0] / 4;
    int octs = B / 8;                             // 8192 point-octets

    cudaFuncSetAttribute(pines_kernel,
                         cudaFuncAttributeMaxDynamicSharedMemorySize,
                         SMEM_BYTES);

    int threads_total = octs * 8;                 // 65536
    int blocks = (threads_total + TPB - 1) / TPB; // 147
    pines_kernel<<<blocks, TPB, SMEM_BYTES>>>(
        (const float4*)inputs, cBar, sBar, (float2*)out, octs);
}

// round 17
// speedup vs baseline: 1.8065x; 1.0942x over previous
#include <cuda_runtime.h>
#include <math.h>

// Pines algorithm, degree N=64, B=65536 — single kernel, one wave.
// R17 = R16 main loop (8 pts/thread = 4 f32x2 chains, 8-way column split
// m = 8c+j, j-interleaved 192B records, register double-buffer prefetch,
// w-rescaled 5-op inner step) with ALL data-independent constants
// (n1', rescale products P, diag, sub, gather indices) computed at
// COMPILE TIME into a __device__ constexpr table (double-precision Newton
// sqrt). The per-block build is now just: coalesced LDG of the record +
// cBar/sBar gather * P + smem stores. No sqrt/scans/barriers in the build.

#define N_DEG 64
#define CDIM  67
#define TPB   448
#define NCH   4

typedef unsigned long long u64;

static __constant__ float c_MU   = 398600441800000.0f;
static __constant__ float c_AREF = 6378136.3f;

// 281 records x 192B (record 280 = zero pad for the last prefetch).
#define NREC       281
#define MAIN_BYTES (NREC * 192)                  // 53952
#define SEED_OFF   MAIN_BYTES                    // 64 x 48B
#define TAIL_OFF   (SEED_OFF + 3072)             // 32B
#define SMEM_BYTES (TAIL_OFF + 32)               // 57056

constexpr int offs_c_h(int c) { return c * (67 - 4 * c); }
__device__ __forceinline__ int offs_c(int c) { return c * (67 - 4 * c); }

// ---------------- compile-time table ----------------
struct __align__(16) Rec  { float n1p, P; int idx, pad; };
struct __align__(16) Seed { float dg, sd; int i0, i1; };

constexpr double csqrt(double x) {
    if (x <= 0.0) return 0.0;
    double y = x, r = 1.0;
    while (y >= 4.0) { y *= 0.25; r *= 2.0; }
    while (y < 1.0)  { y *= 4.0;  r *= 0.5; }
    double s = r * (1.0 + (y - 1.0) * 0.5);
    for (int i = 0; i < 7; ++i) s = 0.5 * (s + x / s);
    return s;
}

struct TabAll {
    Rec  r[NREC * 8];
    Seed s[64];
    float dg64;
    int   pad_;
};

constexpr TabAll make_all() {
    TabAll T{};
    for (int t = 0; t < NREC * 8; ++t) {
        T.r[t].n1p = 0.0f; T.r[t].P = 0.0f; T.r[t].idx = -1; T.r[t].pad = 0;
    }
    double diag[66] = {};
    diag[0] = 1.0;
    for (int l = 1; l <= 65; ++l) {
        double f = (l == 1) ? csqrt(3.0) : csqrt((2.0 * l + 1.0) / (2.0 * l));
        diag[l] = diag[l - 1] * f;
    }
    for (int m = 0; m <= 63; ++m) {
        int c = m >> 3, j = m & 7;
        int l1 = m + 1;
        double sub = (l1 == 1) ? 1.0 : csqrt(2.0 * l1);
        T.s[m].dg = (float)diag[m];
        T.s[m].sd = (float)(sub * diag[m + 1]);
        T.s[m].i0 = (m == 0) ? -1 : m * CDIM + m;   // (0,0) term excluded
        T.s[m].i1 = (m + 1) * CDIM + m;
        int e0 = offs_c_h(c);
        double Pm1 = 1.0, Pm2 = 1.0;   // iw_{l-1}, iw_{l-2}
        for (int k = 0; k <= 62 - m; ++k) {
            int l = m + 2 + k;
            double n1 = csqrt((2.0 * l + 1.0) * (2.0 * l - 1.0) /
                              ((double)(l - m) * (double)(l + m)));
            double n2n = -csqrt((l + m - 1.0) * (2.0 * l + 1.0) * (l - m - 1.0) /
                                ((double)(l + m) * (double)(l - m) * (2.0 * l - 3.0)));
            double P = Pm2 * n2n;                   // iw_l
            int t = (e0 + k) * 8 + j;
            T.r[t].n1p = (float)(n1 * Pm1 / P);
            T.r[t].P   = (float)P;
            T.r[t].idx = l * CDIM + m;
            Pm2 = Pm1; Pm1 = P;
        }
    }
    T.dg64 = (float)diag[64];
    T.pad_ = 0;
    return T;
}

__device__ constexpr TabAll g_T = make_all();

// ---------------------------------------------------------------------------
__device__ __forceinline__ u64 fma2(u64 a, u64 b, u64 c) {
    u64 d; asm("fma.rn.f32x2 %0, %1, %2, %3;" : "=l"(d) : "l"(a), "l"(b), "l"(c));
    return d;
}
__device__ __forceinline__ u64 mul2(u64 a, u64 b) {
    u64 d; asm("mul.rn.f32x2 %0, %1, %2;" : "=l"(d) : "l"(a), "l"(b));
    return d;
}
__device__ __forceinline__ u64 add2(u64 a, u64 b) {
    u64 d; asm("add.rn.f32x2 %0, %1, %2;" : "=l"(d) : "l"(a), "l"(b));
    return d;
}
__device__ __forceinline__ u64 pack2(float lo, float hi) {
    u64 d; asm("mov.b64 %0, {%1, %2};" : "=l"(d) : "f"(lo), "f"(hi));
    return d;
}
__device__ __forceinline__ void unpack2(u64 v, float& lo, float& hi) {
    asm("mov.b64 {%0, %1}, %2;" : "=f"(lo), "=f"(hi) : "l"(v));
}
__device__ __forceinline__ u64 dupf(float x) {
    unsigned int b = __float_as_uint(x);
    return ((u64)b << 32) | (u64)b;
}

// ---------------------------------------------------------------------------
__global__ void __launch_bounds__(TPB)
pines_kernel(const float4* __restrict__ inp,
             const float*  __restrict__ cBar,
             const float*  __restrict__ sBar,
             float2*       __restrict__ out, int octs)
{
    extern __shared__ char smem[];
    int tid = threadIdx.x;

    // ---- trivial table build: precomputed records + cBar/sBar gather ----
    for (int t = tid; t < NREC * 8; t += TPB) {
        Rec r = g_T.r[t];                         // coalesced LDG.128
        float cc = 0.0f, ss = 0.0f;
        if (r.idx >= 0) {
            cc = cBar[r.idx] * r.P;
            ss = sBar[r.idx] * r.P;
        }
        int e = t >> 3, jj = t & 7;
        char* rec = smem + e * 192;
        *(u64*)(rec + jj * 8) = dupf(r.n1p);
        *(ulonglong2*)(rec + 64 + jj * 16) = make_ulonglong2(dupf(cc), dupf(ss));
    }
    if (tid < 64) {
        Seed s = g_T.s[tid];
        float c0 = 0.0f, s0 = 0.0f;
        if (s.i0 >= 0) { c0 = cBar[s.i0]; s0 = sBar[s.i0]; }
        float c1 = cBar[s.i1], s1 = sBar[s.i1];
        ulonglong2* sp = (ulonglong2*)(smem + SEED_OFF + tid * 48);
        sp[0] = make_ulonglong2(dupf(s.dg), dupf(s.sd));
        sp[1] = make_ulonglong2(dupf(c0), dupf(s0));
        sp[2] = make_ulonglong2(dupf(c1), dupf(s1));
    }
    if (tid == TPB - 1) {   // tail record for m = 64
        u64* tp = (u64*)(smem + TAIL_OFF);
        tp[0] = dupf(cBar[64 * CDIM + 64]);
        tp[1] = dupf(sBar[64 * CDIM + 64]);
        tp[2] = dupf(g_T.dg64);
        tp[3] = 0ULL;
    }
    __syncthreads();

    // ========================== main compute =============================
    int g = blockIdx.x * TPB + tid;
    int j = g & 7;          // column-set id within the lane-octet
    int q = g >> 3;         // point-octet index
    bool valid = (q < octs);
    if (!valid) q = octs - 1;

    const float4* pv = inp + 8 * q;

    u64 urho[NCH], rhosq[NCH], rho8[NCH], rm[NCH], acc[NCH];
    u64 cre[NCH], cim[NCH], p8r[NCH], p8i[NCH];
    u64 negone = pack2(-1.0f, -1.0f);

    #pragma unroll
    for (int i = 0; i < NCH; ++i) {
        float4 v0 = pv[2 * i], v1 = pv[2 * i + 1];
        u64 rho = pack2(c_AREF / v0.x, c_AREF / v1.x);
        u64 mu  = pack2(c_MU  / v0.x, c_MU  / v1.x);
        u64 s2  = pack2(v0.y, v1.y);
        u64 t2  = pack2(v0.z, v1.z);
        u64 nt2 = mul2(t2, negone);
        u64 uu  = pack2(v0.w, v1.w);
        urho[i]  = mul2(uu, rho);
        rhosq[i] = mul2(rho, rho);
        u64 rho4 = mul2(rhosq[i], rhosq[i]);
        rho8[i]  = mul2(rho4, rho4);
        // (s+it)^8 by repeated squaring
        u64 p2r = fma2(s2, s2, mul2(nt2, t2));
        u64 st  = mul2(s2, t2);
        u64 p2i = add2(st, st);
        u64 p4r = fma2(p2r, p2r, mul2(mul2(p2i, p2i), negone));
        u64 rr  = mul2(p2r, p2i);
        u64 p4i = add2(rr, rr);
        p8r[i]  = fma2(p4r, p4r, mul2(mul2(p4i, p4i), negone));
        u64 qq  = mul2(p4r, p4i);
        p8i[i]  = add2(qq, qq);
        // start at column m = j
        u64 cr = pack2(1.0f, 1.0f), ci = 0ULL, r = mu;
        for (int it = 0; it < j; ++it) {
            u64 nr = fma2(s2, cr, mul2(nt2, ci));
            u64 ni = fma2(s2, ci, mul2(t2, cr));
            cr = nr; ci = ni;
            r = mul2(r, rho);
        }
        cre[i] = cr; cim[i] = ci; rm[i] = r;
        acc[i] = (j == 0) ? mu : 0ULL;     // MU/r leading term, once
    }

    // ---- column walk: m = 8c + j, c = 0..7 ----
    #pragma unroll 1
    for (int c = 0; c < 8; ++c) {
        const ulonglong2* sp =
            (const ulonglong2*)(smem + SEED_OFF + (c * 8 + j) * 48);
        ulonglong2 dgsd = sp[0], cs0 = sp[1], cs1 = sp[2];

        u64 b1[NCH], b2[NCH], aC[NCH], aS[NCH];
        #pragma unroll
        for (int i = 0; i < NCH; ++i) {
            b2[i] = mul2(rm[i], dgsd.x);                     // l = m   (w=1)
            b1[i] = mul2(mul2(rm[i], urho[i]), dgsd.y);      // l = m+1 (w=1)
            aC[i] = mul2(b2[i], cs0.x);
            aS[i] = mul2(b2[i], cs0.y);
            aC[i] = fma2(b1[i], cs1.x, aC[i]);
            aS[i] = fma2(b1[i], cs1.y, aS[i]);
        }

        const char* pj8  = smem + offs_c(c) * 192 + j * 8;
        const char* pj16 = smem + offs_c(c) * 192 + 64 + j * 16;
        int n = 63 - 8 * c;                                  // uniform (padded)

        // software pipeline: prefetch record k+1, compute record k
        u64        n1_c = *(const u64*)(pj8);
        ulonglong2 cs_c = *(const ulonglong2*)(pj16);
        pj8 += 192; pj16 += 192;

        #pragma unroll 2
        for (int k = 0; k < n - 1; ++k) {
            u64        n1_x = *(const u64*)(pj8);
            ulonglong2 cs_x = *(const ulonglong2*)(pj16);
            pj8 += 192; pj16 += 192;
            #pragma unroll
            for (int i = 0; i < NCH; ++i) {
                u64 t2 = mul2(rhosq[i], b2[i]);      // off critical path
                u64 m1 = mul2(n1_c, b1[i]);          // critical
                u64 b  = fma2(urho[i], m1, t2);
                aC[i] = fma2(b, cs_c.x, aC[i]);
                aS[i] = fma2(b, cs_c.y, aS[i]);
                b2[i] = b1[i];
                b1[i] = b;
            }
            n1_c = n1_x;
            cs_c = cs_x;
        }
        // last record of this column block
        #pragma unroll
        for (int i = 0; i < NCH; ++i) {
            u64 t2 = mul2(rhosq[i], b2[i]);
            u64 m1 = mul2(n1_c, b1[i]);
            u64 b  = fma2(urho[i], m1, t2);
            aC[i] = fma2(b, cs_c.x, aC[i]);
            aS[i] = fma2(b, cs_c.y, aS[i]);
            b2[i] = b1[i];
            b1[i] = b;
        }

        #pragma unroll
        for (int i = 0; i < NCH; ++i) {
            acc[i] = fma2(cre[i], aC[i], acc[i]);
            acc[i] = fma2(cim[i], aS[i], acc[i]);
            // jump 8 columns: phasor *= (s+it)^8, rm *= rho^8
            u64 nr = fma2(mul2(cim[i], p8i[i]), negone, mul2(cre[i], p8r[i]));
            u64 ni = fma2(cim[i], p8r[i], mul2(cre[i], p8i[i]));
            cre[i] = nr; cim[i] = ni;
            rm[i] = mul2(rm[i], rho8[i]);
        }
    }

    // tail column m = 64 (j==0 lanes are exactly at m=64 now)
    if (j == 0) {
        const u64* tp = (const u64*)(smem + TAIL_OFF);
        u64 c64 = tp[0], s64 = tp[1], dg64 = tp[2];
        #pragma unroll
        for (int i = 0; i < NCH; ++i) {
            u64 b = mul2(rm[i], dg64);
            acc[i] = fma2(cre[i], mul2(b, c64), acc[i]);
            acc[i] = fma2(cim[i], mul2(b, s64), acc[i]);
        }
    }

    // combine 8 column-set partials within each lane-octet
    #pragma unroll
    for (int i = 0; i < NCH; ++i) {
        u64 a = acc[i];
        a = add2(a, __shfl_xor_sync(0xffffffffu, a, 1));
        a = add2(a, __shfl_xor_sync(0xffffffffu, a, 2));
        a = add2(a, __shfl_xor_sync(0xffffffffu, a, 4));
        acc[i] = a;
    }

    if (valid && j == 0) {
        #pragma unroll
        for (int i = 0; i < NCH; ++i) {
            float lo, hi;
            unpack2(acc[i], lo, hi);
            out[4 * q + i] = make_float2(-lo, -hi);
        }
    }
}

// ---------------------------------------------------------------------------
extern "C" void kernel_launch(void* const* d_in, const int* in_sizes, int n_in,
                              void* d_out, int out_size)
{
    const float* inputs = (const float*)d_in[0];  // [B,4] : r,s,t,u
    const float* cBar   = (const float*)d_in[1];  // [67,67]
    const float* sBar   = (const float*)d_in[2];  // [67,67]
    float*       out    = (float*)d_out;          // [B]

    int B    = in_sizes[0] / 4;
    int octs = B / 8;                             // 8192 point-octets

    cudaFuncSetAttribute(pines_kernel,
                         cudaFuncAttributeMaxDynamicSharedMemorySize,
                         SMEM_BYTES);

    int threads_total = octs * 8;                 // 65536
    int blocks = (threads_total + TPB - 1) / TPB; // 147
    pines_kernel<<<blocks, TPB, SMEM_BYTES>>>(
        (const float4*)inputs, cBar, sBar, (float2*)out, octs);
}